// round 10
// baseline (speedup 1.0000x reference)
#include <cuda_runtime.h>
#include <math.h>

#define NAT   2048
#define NG    8
#define NE    4
#define NPERM 10
#define FEATN 672
#define RCf   6.0f
#define RCAf  4.0f
#define RC2f  36.0f
#define RCA2f 16.0f
#define PI_F  3.14159265358979f

#define BLK_A  128
#define NWARP  4
#define SLAB   512          // NAT / NWARP candidates per warp
#define CAP    72           // per-warp list capacity (exp ~21 B / ~9 A, >10 sigma)
#define MAXN   288          // NWARP * CAP
#define PSTR   36           // padded fields per pair (16B-aligned rows)

#define BM 64
#define BK 8
#define KSPLIT 4
#define KPER  168           // 672 / 4

// scratch (static device globals: allocation-free, graph-safe)
__device__ __align__(16) float g_feat[NAT * FEATN];
__device__ __align__(16) float g_h1p[KSPLIT * NAT * 64];
__device__ __align__(16) float g_posT[3 * NAT];     // SoA positions

// ---------------------------------------------------------------------------
// Kernel P: transpose positions [NAT,3] -> SoA [3][NAT] (coalesced scan loads)
// ---------------------------------------------------------------------------
__global__ void posT_kernel(const float* __restrict__ pos)
{
    int t = blockIdx.x * blockDim.x + threadIdx.x;      // 0 .. 3*NAT-1
    if (t < 3 * NAT) {
        int d = t / NAT, j = t - d * NAT;
        g_posT[t] = __ldg(&pos[3 * j + d]);
    }
}

// ---------------------------------------------------------------------------
// Kernel A: per-atom feature construction (warp-segmented neighbor compaction)
// pbuf fields per pair k: [0..7]=rad, [8..15]=rad_ang, [16..20]=ang p0..p4,
// [24..28]=ang p5..p9, [32..35]=spec_i*spec_j
// ---------------------------------------------------------------------------
__global__ __launch_bounds__(BLK_A) void feat_kernel(
    const float* __restrict__ pos,
    const float* __restrict__ spec,
    const float* __restrict__ kn_rad, const float* __restrict__ kn_ang,
    const float* __restrict__ rbf_w,  const float* __restrict__ rbf_b,
    const float* __restrict__ rbf_aw, const float* __restrict__ rbf_ab)
{
    __shared__ __align__(16) float pbuf[MAXN * PSTR];
    __shared__ int jlA[NWARP][CAP], jlB[NWARP][CAP];
    __shared__ int cAs[NWARP], cBs[NWARP];
    __shared__ float knr[NG], kna[NG], wr[NG], br[NG], wa[NG], ba[NG];
    __shared__ float sp_i[NE];
    __shared__ float radw3[32];                // warp3's partial radial sums

    const int i    = blockIdx.x;
    const int tid  = threadIdx.x;
    const int lane = tid & 31;
    const int warp = tid >> 5;

    if (tid < NG) {
        knr[tid] = (PI_F / RCf)  * (float)(tid + 1) * kn_rad[tid];
        kna[tid] = (PI_F / RCAf) * (float)(tid + 1) * kn_ang[tid];
        wr[tid] = rbf_w[tid];  br[tid] = rbf_b[tid];
        wa[tid] = rbf_aw[tid]; ba[tid] = rbf_ab[tid];
    }
    if (tid < NE) sp_i[tid] = spec[i * NE + tid];

    const float xi = pos[3*i], yi = pos[3*i+1], zi = pos[3*i+2];
    const float* __restrict__ px = &g_posT[0];
    const float* __restrict__ py = &g_posT[NAT];
    const float* __restrict__ pz = &g_posT[2 * NAT];

    // ---- warp-segmented compaction: no barriers during the O(N) scan ----
    // cutoff test in r^2 space (no sqrt); coalesced SoA loads.
    // order (warp, round, lane) is deterministic across replays.
    {
        int cA = 0, cB = 0;            // warp-uniform running counts
        const int jbase = warp * SLAB;
        #pragma unroll 1
        for (int rnd = 0; rnd < SLAB / 32; rnd++) {
            int j = jbase + rnd * 32 + lane;
            float dx = xi - px[j], dy = yi - py[j], dz = zi - pz[j];
            float r2 = dx*dx + dy*dy + dz*dz;
            bool actA = (r2 <= RCA2f) && (r2 > 0.0f);
            bool actB = (r2 <= RC2f)  && (r2 > RCA2f);
            unsigned mA = __ballot_sync(0xffffffffu, actA);
            unsigned mB = __ballot_sync(0xffffffffu, actB);
            unsigned lt = (1u << lane) - 1u;
            if (actA) { int p = cA + __popc(mA & lt); if (p < CAP) jlA[warp][p] = j; }
            if (actB) { int p = cB + __popc(mB & lt); if (p < CAP) jlB[warp][p] = j; }
            cA += __popc(mA); cB += __popc(mB);
        }
        if (lane == 0) {
            cAs[warp] = (cA < CAP) ? cA : CAP;
            cBs[warp] = (cB < CAP) ? cB : CAP;
        }
    }
    __syncthreads();

    // prefix sums over segments (registers, every thread)
    int pA[NWARP + 1], pB[NWARP + 1];
    pA[0] = 0;
    #pragma unroll
    for (int w = 0; w < NWARP; w++) pA[w + 1] = pA[w] + cAs[w];
    pB[0] = pA[NWARP];
    #pragma unroll
    for (int w = 0; w < NWARP; w++) pB[w + 1] = pB[w] + cBs[w];
    const int nA = pA[NWARP], nT = pB[NWARP];

    // ---- heavy fill pass 1: angular pairs (k < nA), branch-free body ----
    for (int k = tid; k < nA; k += BLK_A) {
        int w = 0;
        while (k >= pA[w + 1]) w++;
        int j = jlA[w][k - pA[w]];
        float dx = xi - px[j], dy = yi - py[j], dz = zi - pz[j];
        float r2 = dx*dx + dy*dy + dz*dz;
        float r  = sqrtf(r2 + 1e-16f);
        float rinv = __fdividef(1.0f, r);
        float* pb = &pbuf[k * PSTR];
        float fc  = 0.5f * (__cosf((PI_F / RCf)  * r) + 1.0f);
        float fca = 0.5f * (__cosf((PI_F / RCAf) * r) + 1.0f);
        #pragma unroll
        for (int l = 0; l < NG; l++) {
            float s = __sinf(knr[l] * r);
            float g = __fdividef(1.0f, 1.0f + __expf(-(r * wr[l] + br[l])));
            pb[l] = s * rinv * fc * g;
        }
        #pragma unroll
        for (int l = 0; l < NG; l++) {
            float s = __sinf(kna[l] * r);
            float g = __fdividef(1.0f, 1.0f + __expf(-(r * wa[l] + ba[l])));
            pb[8 + l] = s * rinv * fca * g;
        }
        float4 sj = __ldg(&reinterpret_cast<const float4*>(spec)[j]);
        pb[32] = sp_i[0] * sj.x; pb[33] = sp_i[1] * sj.y;
        pb[34] = sp_i[2] * sj.z; pb[35] = sp_i[3] * sj.w;
        float ux = dx * rinv, uy = dy * rinv, uz = dz * rinv;
        pb[16] = 1.0f;    pb[17] = uz;      pb[18] = uy;
        pb[19] = ux;      pb[20] = uz * uz;
        pb[24] = uy * uz; pb[25] = uy * uy; pb[26] = ux * uz;
        pb[27] = ux * uy; pb[28] = ux * ux;
    }

    // ---- heavy fill pass 2: radial-only pairs (nA <= k < nT) ----
    for (int k = nA + tid; k < nT; k += BLK_A) {
        int w = 0;
        while (k >= pB[w + 1]) w++;
        int j = jlB[w][k - pB[w]];
        float dx = xi - px[j], dy = yi - py[j], dz = zi - pz[j];
        float r2 = dx*dx + dy*dy + dz*dz;
        float r  = sqrtf(r2 + 1e-16f);
        float rinv = __fdividef(1.0f, r);
        float* pb = &pbuf[k * PSTR];
        float fc = 0.5f * (__cosf((PI_F / RCf) * r) + 1.0f);
        #pragma unroll
        for (int l = 0; l < NG; l++) {
            float s = __sinf(knr[l] * r);
            float g = __fdividef(1.0f, 1.0f + __expf(-(r * wr[l] + br[l])));
            pb[l] = s * rinv * fc * g;
        }
        float4 sj = __ldg(&reinterpret_cast<const float4*>(spec)[j]);
        pb[32] = sp_i[0] * sj.x; pb[33] = sp_i[1] * sj.y;
        pb[34] = sp_i[2] * sj.z; pb[35] = sp_i[3] * sj.w;
    }
    __syncthreads();

    // ---- accumulate (output-owning threads) ----
    //  warps 0,1: M[l, p in warp*5..warp*5+4, e], l = lane&7, e = lane>>3
    //  warps 2,3: G[l, e] split over pair halves (deterministic combine)
    const int ol = lane & 7, oe = lane >> 3;
    float acc0 = 0.f, acc1 = 0.f, acc2 = 0.f, acc3 = 0.f, acc4 = 0.f;

    if (warp < 2) {
        const int angb = 16 + warp * 8;   // 16 or 24
        for (int k = 0; k < nA; k++) {
            const float* pb = &pbuf[k * PSTR];
            float t  = pb[8 + ol] * pb[32 + oe];
            float4 a4 = *reinterpret_cast<const float4*>(pb + angb);
            float  a5 = pb[angb + 4];
            acc0 += t * a4.x; acc1 += t * a4.y; acc2 += t * a4.z;
            acc3 += t * a4.w; acc4 += t * a5;
        }
    } else {
        // warps 2,3 split the radial pair range deterministically;
        // two accumulators (even/odd) halve the FFMA RAW chain depth.
        const int half = nT >> 1;
        const int k0 = (warp == 2) ? 0 : half;
        const int k1 = (warp == 2) ? half : nT;
        float aE = 0.f, aO = 0.f;
        int k = k0;
        for (; k + 1 < k1; k += 2) {
            const float* p0 = &pbuf[k * PSTR];
            const float* p1 = &pbuf[(k + 1) * PSTR];
            aE += p0[ol] * p0[32 + oe];
            aO += p1[ol] * p1[32 + oe];
        }
        if (k < k1) {
            const float* p0 = &pbuf[k * PSTR];
            aE += p0[ol] * p0[32 + oe];
        }
        acc0 = aE + aO;                 // fixed combine order
    }

    // ---- combine warp3 radial partial into warp2 (fixed order) ----
    if (warp == 3) radw3[lane] = acc0;
    __syncthreads();
    if (warp == 2) acc0 += radw3[lane];

    // ---- write features ----
    float* fo = &g_feat[i * FEATN];
    if (warp < 2) {
        int base = 32 + ol * (NPERM * NE) + (warp * 5) * NE + oe;  // M[l,p0,e]
        fo[base +  0] = acc0; fo[base +  4] = acc1; fo[base +  8] = acc2;
        fo[base + 12] = acc3; fo[base + 16] = acc4;
        int b2i = base + NG * NPERM * NE;                          // +320 -> M^2
        fo[b2i +  0] = acc0 * acc0; fo[b2i +  4] = acc1 * acc1;
        fo[b2i +  8] = acc2 * acc2; fo[b2i + 12] = acc3 * acc3;
        fo[b2i + 16] = acc4 * acc4;
    } else if (warp == 2) {
        fo[ol * NE + oe] = acc0;                                   // G[l,e]
    }
}

// ---------------------------------------------------------------------------
// Kernel B: split-K SGEMM partials: g_h1p[s] = feat[:, ks] @ W1[ks, :]
// ---------------------------------------------------------------------------
__global__ __launch_bounds__(256) void gemm1_kernel(const float* __restrict__ W1)
{
    __shared__ __align__(16) float As[BK][68];
    __shared__ __align__(16) float Bs[BK][68];
    const int m0  = blockIdx.x * BM;
    const int ks0 = blockIdx.y * KPER;
    const int tid = threadIdx.x;
    const int ty  = tid >> 4, tx = tid & 15;

    float acc[4][4] = {};

    for (int k0 = 0; k0 < KPER; k0 += BK) {
        #pragma unroll
        for (int t = 0; t < 2; t++) {
            int lin = tid + t * 256;
            int m = lin >> 3, kk = lin & 7;
            As[kk][m] = g_feat[(m0 + m) * FEATN + ks0 + k0 + kk];
        }
        #pragma unroll
        for (int t = 0; t < 2; t++) {
            int lin = tid + t * 256;
            int n = lin & 63, kk = lin >> 6;
            Bs[kk][n] = __ldg(&W1[(ks0 + k0 + kk) * 64 + n]);
        }
        __syncthreads();
        #pragma unroll
        for (int kk = 0; kk < BK; kk++) {
            float4 a = *reinterpret_cast<const float4*>(&As[kk][ty * 4]);
            float4 b = *reinterpret_cast<const float4*>(&Bs[kk][tx * 4]);
            acc[0][0] += a.x * b.x; acc[0][1] += a.x * b.y; acc[0][2] += a.x * b.z; acc[0][3] += a.x * b.w;
            acc[1][0] += a.y * b.x; acc[1][1] += a.y * b.y; acc[1][2] += a.y * b.z; acc[1][3] += a.y * b.w;
            acc[2][0] += a.z * b.x; acc[2][1] += a.z * b.y; acc[2][2] += a.z * b.z; acc[2][3] += a.z * b.w;
            acc[3][0] += a.w * b.x; acc[3][1] += a.w * b.y; acc[3][2] += a.w * b.z; acc[3][3] += a.w * b.w;
        }
        __syncthreads();
    }

    float* outp = &g_h1p[blockIdx.y * NAT * 64];
    #pragma unroll
    for (int ii = 0; ii < 4; ii++) {
        int row = m0 + ty * 4 + ii;
        float4 v = make_float4(acc[ii][0], acc[ii][1], acc[ii][2], acc[ii][3]);
        *reinterpret_cast<float4*>(&outp[row * 64 + tx * 4]) = v;
    }
}

// ---------------------------------------------------------------------------
// Kernel C: split-K reduce + b1 + tanh, layer2 (tanh), layer3 dot -> e_atom
// 4 atoms per CTA, 256 threads (64 per atom)
// ---------------------------------------------------------------------------
__global__ __launch_bounds__(256) void mlp23_kernel(
    const float* __restrict__ b1, const float* __restrict__ W2,
    const float* __restrict__ b2, const float* __restrict__ W3,
    const float* __restrict__ b3, float* __restrict__ out)
{
    __shared__ float W2s[64][65];
    __shared__ float h1s[4][64];
    __shared__ float red[8];

    const int tid = threadIdx.x;
    const int a = tid >> 6, o = tid & 63;
    const int atom = blockIdx.x * 4 + a;

    #pragma unroll
    for (int t = 0; t < 16; t++) {
        int lin = tid + t * 256;
        W2s[lin >> 6][lin & 63] = __ldg(&W2[lin]);
    }

    float pre = b1[o];
    #pragma unroll
    for (int s = 0; s < KSPLIT; s++) pre += g_h1p[s * NAT * 64 + atom * 64 + o];
    h1s[a][o] = tanhf(pre);
    __syncthreads();

    float acc = b2[o];
    #pragma unroll
    for (int k = 0; k < 64; k++) acc += h1s[a][k] * W2s[k][o];
    float v = tanhf(acc) * W3[o];

    #pragma unroll
    for (int d = 16; d > 0; d >>= 1) v += __shfl_down_sync(0xffffffffu, v, d);
    const int warp = tid >> 5;
    if ((tid & 31) == 0) red[warp] = v;
    __syncthreads();
    if (o == 0) out[atom] = red[2 * a] + red[2 * a + 1] + b3[0];
}

// ---------------------------------------------------------------------------
extern "C" void kernel_launch(void* const* d_in, const int* in_sizes, int n_in,
                              void* d_out, int out_size)
{
    const float* pos    = (const float*)d_in[0];
    const float* spec   = (const float*)d_in[1];
    const float* kn_rad = (const float*)d_in[2];
    const float* kn_ang = (const float*)d_in[3];
    const float* rbf_w  = (const float*)d_in[4];
    const float* rbf_b  = (const float*)d_in[5];
    const float* rbf_aw = (const float*)d_in[6];
    const float* rbf_ab = (const float*)d_in[7];
    const float* W1     = (const float*)d_in[8];
    const float* b1     = (const float*)d_in[9];
    const float* W2     = (const float*)d_in[10];
    const float* b2     = (const float*)d_in[11];
    const float* W3     = (const float*)d_in[12];
    const float* b3     = (const float*)d_in[13];

    posT_kernel<<<(3 * NAT + 255) / 256, 256>>>(pos);
    feat_kernel<<<NAT, BLK_A>>>(pos, spec, kn_rad, kn_ang,
                                rbf_w, rbf_b, rbf_aw, rbf_ab);
    dim3 gb(NAT / BM, KSPLIT);
    gemm1_kernel<<<gb, 256>>>(W1);
    mlp23_kernel<<<NAT / 4, 256>>>(b1, W2, b2, W3, b3, (float*)d_out);
}

// round 13
// speedup vs baseline: 1.0457x; 1.0457x over previous
#include <cuda_runtime.h>
#include <math.h>

#define NAT   2048
#define NG    8
#define NE    4
#define NPERM 10
#define FEATN 672
#define RCf   6.0f
#define RCAf  4.0f
#define RC2f  36.0f
#define RCA2f 16.0f
#define PI_F  3.14159265358979f

#define BLK_A  128
#define NWARP  4
#define SLAB   512          // NAT / NWARP candidates per warp
#define CAP    72           // per-warp list capacity (exp ~21 B / ~9 A, >10 sigma)
#define MAXN   288          // NWARP * CAP
#define PSTR   36           // padded fields per pair (16B-aligned rows)

#define BM 64
#define BKg 4
#define KSPLIT 8
#define KPER  84            // 672 / 8

// scratch (static device globals: allocation-free, graph-safe)
__device__ __align__(16) float g_feat[NAT * FEATN];
__device__ __align__(16) float g_h1p[KSPLIT * NAT * 64];
__device__ __align__(16) float g_posT[3 * NAT];     // SoA positions

// ---------------------------------------------------------------------------
// Kernel P: transpose positions [NAT,3] -> SoA [3][NAT] (coalesced scan loads)
// ---------------------------------------------------------------------------
__global__ void posT_kernel(const float* __restrict__ pos)
{
    int t = blockIdx.x * blockDim.x + threadIdx.x;      // 0 .. 3*NAT-1
    if (t < 3 * NAT) {
        int d = t / NAT, j = t - d * NAT;
        g_posT[t] = __ldg(&pos[3 * j + d]);
    }
}

// ---------------------------------------------------------------------------
// Kernel A: per-atom feature construction (warp-segmented neighbor compaction)
// pbuf fields per pair k: [0..7]=rad, [8..15]=rad_ang, [16..20]=ang p0..p4,
// [24..28]=ang p5..p9, [32..35]=spec_i*spec_j
// ---------------------------------------------------------------------------
__global__ __launch_bounds__(BLK_A) void feat_kernel(
    const float* __restrict__ pos,
    const float* __restrict__ spec,
    const float* __restrict__ kn_rad, const float* __restrict__ kn_ang,
    const float* __restrict__ rbf_w,  const float* __restrict__ rbf_b,
    const float* __restrict__ rbf_aw, const float* __restrict__ rbf_ab)
{
    __shared__ __align__(16) float pbuf[MAXN * PSTR];
    __shared__ int jlA[NWARP][CAP], jlB[NWARP][CAP];
    __shared__ int cAs[NWARP], cBs[NWARP];
    __shared__ float knr[NG], kna[NG], wr[NG], br[NG], wa[NG], ba[NG];
    __shared__ float sp_i[NE];
    __shared__ float radw3[32];                // warp3's partial radial sums

    const int i    = blockIdx.x;
    const int tid  = threadIdx.x;
    const int lane = tid & 31;
    const int warp = tid >> 5;

    if (tid < NG) {
        knr[tid] = (PI_F / RCf)  * (float)(tid + 1) * kn_rad[tid];
        kna[tid] = (PI_F / RCAf) * (float)(tid + 1) * kn_ang[tid];
        wr[tid] = rbf_w[tid];  br[tid] = rbf_b[tid];
        wa[tid] = rbf_aw[tid]; ba[tid] = rbf_ab[tid];
    }
    if (tid < NE) sp_i[tid] = spec[i * NE + tid];

    const float xi = pos[3*i], yi = pos[3*i+1], zi = pos[3*i+2];
    const float* __restrict__ px = &g_posT[0];
    const float* __restrict__ py = &g_posT[NAT];
    const float* __restrict__ pz = &g_posT[2 * NAT];

    // ---- warp-segmented compaction: no barriers during the O(N) scan ----
    {
        int cA = 0, cB = 0;            // warp-uniform running counts
        const int jbase = warp * SLAB;
        #pragma unroll 1
        for (int rnd = 0; rnd < SLAB / 32; rnd++) {
            int j = jbase + rnd * 32 + lane;
            float dx = xi - px[j], dy = yi - py[j], dz = zi - pz[j];
            float r2 = dx*dx + dy*dy + dz*dz;
            bool actA = (r2 <= RCA2f) && (r2 > 0.0f);
            bool actB = (r2 <= RC2f)  && (r2 > RCA2f);
            unsigned mA = __ballot_sync(0xffffffffu, actA);
            unsigned mB = __ballot_sync(0xffffffffu, actB);
            unsigned lt = (1u << lane) - 1u;
            if (actA) { int p = cA + __popc(mA & lt); if (p < CAP) jlA[warp][p] = j; }
            if (actB) { int p = cB + __popc(mB & lt); if (p < CAP) jlB[warp][p] = j; }
            cA += __popc(mA); cB += __popc(mB);
        }
        if (lane == 0) {
            cAs[warp] = (cA < CAP) ? cA : CAP;
            cBs[warp] = (cB < CAP) ? cB : CAP;
        }
    }
    __syncthreads();

    // prefix sums as NAMED SCALARS (no dynamically-indexed register arrays ->
    // no local-memory demotion)
    const int a1 = cAs[0];
    const int a2 = a1 + cAs[1];
    const int a3 = a2 + cAs[2];
    const int nA = a3 + cAs[3];
    const int b1v = nA + cBs[0];
    const int b2v = b1v + cBs[1];
    const int b3v = b2v + cBs[2];
    const int nT  = b3v + cBs[3];

    // ---- heavy fill pass 1: angular pairs (k < nA), branchless seg lookup ----
    for (int k = tid; k < nA; k += BLK_A) {
        int w = (k >= a1) + (k >= a2) + (k >= a3);
        int base = (w == 0) ? 0 : ((w == 1) ? a1 : ((w == 2) ? a2 : a3));
        int j = jlA[w][k - base];
        float dx = xi - px[j], dy = yi - py[j], dz = zi - pz[j];
        float r2 = dx*dx + dy*dy + dz*dz;
        float r  = sqrtf(r2 + 1e-16f);
        float rinv = __fdividef(1.0f, r);
        float* pb = &pbuf[k * PSTR];
        float fc  = 0.5f * (__cosf((PI_F / RCf)  * r) + 1.0f);
        float fca = 0.5f * (__cosf((PI_F / RCAf) * r) + 1.0f);
        #pragma unroll
        for (int l = 0; l < NG; l++) {
            float s = __sinf(knr[l] * r);
            float g = __fdividef(1.0f, 1.0f + __expf(-(r * wr[l] + br[l])));
            pb[l] = s * rinv * fc * g;
        }
        #pragma unroll
        for (int l = 0; l < NG; l++) {
            float s = __sinf(kna[l] * r);
            float g = __fdividef(1.0f, 1.0f + __expf(-(r * wa[l] + ba[l])));
            pb[8 + l] = s * rinv * fca * g;
        }
        float4 sj = __ldg(&reinterpret_cast<const float4*>(spec)[j]);
        pb[32] = sp_i[0] * sj.x; pb[33] = sp_i[1] * sj.y;
        pb[34] = sp_i[2] * sj.z; pb[35] = sp_i[3] * sj.w;
        float ux = dx * rinv, uy = dy * rinv, uz = dz * rinv;
        pb[16] = 1.0f;    pb[17] = uz;      pb[18] = uy;
        pb[19] = ux;      pb[20] = uz * uz;
        pb[24] = uy * uz; pb[25] = uy * uy; pb[26] = ux * uz;
        pb[27] = ux * uy; pb[28] = ux * ux;
    }

    // ---- heavy fill pass 2: radial-only pairs (nA <= k < nT) ----
    for (int k = nA + tid; k < nT; k += BLK_A) {
        int w = (k >= b1v) + (k >= b2v) + (k >= b3v);
        int base = (w == 0) ? nA : ((w == 1) ? b1v : ((w == 2) ? b2v : b3v));
        int j = jlB[w][k - base];
        float dx = xi - px[j], dy = yi - py[j], dz = zi - pz[j];
        float r2 = dx*dx + dy*dy + dz*dz;
        float r  = sqrtf(r2 + 1e-16f);
        float rinv = __fdividef(1.0f, r);
        float* pb = &pbuf[k * PSTR];
        float fc = 0.5f * (__cosf((PI_F / RCf) * r) + 1.0f);
        #pragma unroll
        for (int l = 0; l < NG; l++) {
            float s = __sinf(knr[l] * r);
            float g = __fdividef(1.0f, 1.0f + __expf(-(r * wr[l] + br[l])));
            pb[l] = s * rinv * fc * g;
        }
        float4 sj = __ldg(&reinterpret_cast<const float4*>(spec)[j]);
        pb[32] = sp_i[0] * sj.x; pb[33] = sp_i[1] * sj.y;
        pb[34] = sp_i[2] * sj.z; pb[35] = sp_i[3] * sj.w;
    }
    __syncthreads();

    // ---- accumulate (output-owning threads) ----
    const int ol = lane & 7, oe = lane >> 3;
    float acc0 = 0.f, acc1 = 0.f, acc2 = 0.f, acc3 = 0.f, acc4 = 0.f;

    if (warp < 2) {
        const int angb = 16 + warp * 8;   // 16 or 24
        for (int k = 0; k < nA; k++) {
            const float* pb = &pbuf[k * PSTR];
            float t  = pb[8 + ol] * pb[32 + oe];
            float4 a4 = *reinterpret_cast<const float4*>(pb + angb);
            float  a5 = pb[angb + 4];
            acc0 += t * a4.x; acc1 += t * a4.y; acc2 += t * a4.z;
            acc3 += t * a4.w; acc4 += t * a5;
        }
    } else {
        const int half = nT >> 1;
        const int k0 = (warp == 2) ? 0 : half;
        const int k1 = (warp == 2) ? half : nT;
        float aE = 0.f, aO = 0.f;
        int k = k0;
        for (; k + 1 < k1; k += 2) {
            const float* p0 = &pbuf[k * PSTR];
            const float* p1 = &pbuf[(k + 1) * PSTR];
            aE += p0[ol] * p0[32 + oe];
            aO += p1[ol] * p1[32 + oe];
        }
        if (k < k1) {
            const float* p0 = &pbuf[k * PSTR];
            aE += p0[ol] * p0[32 + oe];
        }
        acc0 = aE + aO;                 // fixed combine order
    }

    if (warp == 3) radw3[lane] = acc0;
    __syncthreads();
    if (warp == 2) acc0 += radw3[lane];

    float* fo = &g_feat[i * FEATN];
    if (warp < 2) {
        int base = 32 + ol * (NPERM * NE) + (warp * 5) * NE + oe;  // M[l,p0,e]
        fo[base +  0] = acc0; fo[base +  4] = acc1; fo[base +  8] = acc2;
        fo[base + 12] = acc3; fo[base + 16] = acc4;
        int b2i = base + NG * NPERM * NE;                          // +320 -> M^2
        fo[b2i +  0] = acc0 * acc0; fo[b2i +  4] = acc1 * acc1;
        fo[b2i +  8] = acc2 * acc2; fo[b2i + 12] = acc3 * acc3;
        fo[b2i + 16] = acc4 * acc4;
    } else if (warp == 2) {
        fo[ol * NE + oe] = acc0;                                   // G[l,e]
    }
}

// ---------------------------------------------------------------------------
// Kernel B: split-K SGEMM, register-prefetch double buffering.
// g_h1p[s] = feat[:, ks] @ W1[ks, :];  grid (32, 8) = 256 CTAs.
// ---------------------------------------------------------------------------
__global__ __launch_bounds__(256) void gemm1_kernel(const float* __restrict__ W1)
{
    __shared__ __align__(16) float As[2][BKg][68];
    __shared__ __align__(16) float Bs[2][BKg][68];
    const int m0  = blockIdx.x * BM;
    const int ks0 = blockIdx.y * KPER;
    const int tid = threadIdx.x;
    const int ty  = tid >> 4, tx = tid & 15;
    const int lm = tid >> 2, lk = tid & 3;     // As loader: 64 m x 4 kk
    const int bk = tid >> 6, bn = tid & 63;    // Bs loader: 4 kk x 64 n

    float acc[4][4] = {};

    // preload tile 0
    float a_reg = g_feat[(m0 + lm) * FEATN + ks0 + lk];
    float b_reg = __ldg(&W1[(ks0 + bk) * 64 + bn]);
    As[0][lk][lm] = a_reg;
    Bs[0][bk][bn] = b_reg;
    __syncthreads();

    int buf = 0;
    for (int k0 = BKg; k0 < KPER; k0 += BKg) {
        // prefetch next tile into registers
        a_reg = g_feat[(m0 + lm) * FEATN + ks0 + k0 + lk];
        b_reg = __ldg(&W1[(ks0 + k0 + bk) * 64 + bn]);
        // compute current tile
        #pragma unroll
        for (int kk = 0; kk < BKg; kk++) {
            float4 a = *reinterpret_cast<const float4*>(&As[buf][kk][ty * 4]);
            float4 b = *reinterpret_cast<const float4*>(&Bs[buf][kk][tx * 4]);
            acc[0][0] += a.x * b.x; acc[0][1] += a.x * b.y; acc[0][2] += a.x * b.z; acc[0][3] += a.x * b.w;
            acc[1][0] += a.y * b.x; acc[1][1] += a.y * b.y; acc[1][2] += a.y * b.z; acc[1][3] += a.y * b.w;
            acc[2][0] += a.z * b.x; acc[2][1] += a.z * b.y; acc[2][2] += a.z * b.z; acc[2][3] += a.z * b.w;
            acc[3][0] += a.w * b.x; acc[3][1] += a.w * b.y; acc[3][2] += a.w * b.z; acc[3][3] += a.w * b.w;
        }
        // stage next tile into the other buffer
        As[buf ^ 1][lk][lm] = a_reg;
        Bs[buf ^ 1][bk][bn] = b_reg;
        __syncthreads();
        buf ^= 1;
    }
    // final tile
    #pragma unroll
    for (int kk = 0; kk < BKg; kk++) {
        float4 a = *reinterpret_cast<const float4*>(&As[buf][kk][ty * 4]);
        float4 b = *reinterpret_cast<const float4*>(&Bs[buf][kk][tx * 4]);
        acc[0][0] += a.x * b.x; acc[0][1] += a.x * b.y; acc[0][2] += a.x * b.z; acc[0][3] += a.x * b.w;
        acc[1][0] += a.y * b.x; acc[1][1] += a.y * b.y; acc[1][2] += a.y * b.z; acc[1][3] += a.y * b.w;
        acc[2][0] += a.z * b.x; acc[2][1] += a.z * b.y; acc[2][2] += a.z * b.z; acc[2][3] += a.z * b.w;
        acc[3][0] += a.w * b.x; acc[3][1] += a.w * b.y; acc[3][2] += a.w * b.z; acc[3][3] += a.w * b.w;
    }

    float* outp = &g_h1p[blockIdx.y * NAT * 64];
    #pragma unroll
    for (int ii = 0; ii < 4; ii++) {
        int row = m0 + ty * 4 + ii;
        float4 v = make_float4(acc[ii][0], acc[ii][1], acc[ii][2], acc[ii][3]);
        *reinterpret_cast<float4*>(&outp[row * 64 + tx * 4]) = v;
    }
}

// ---------------------------------------------------------------------------
// Kernel C: split-K reduce + b1 + tanh, layer2 (tanh), layer3 dot -> e_atom
// 16 atoms per CTA (4 batches of 4), W2 loaded ONCE per 16 atoms. 128 CTAs.
// ---------------------------------------------------------------------------
__global__ __launch_bounds__(256) void mlp23_kernel(
    const float* __restrict__ b1, const float* __restrict__ W2,
    const float* __restrict__ b2, const float* __restrict__ W3,
    const float* __restrict__ b3, float* __restrict__ out)
{
    __shared__ float W2s[64][65];
    __shared__ float h1s[4][64];
    __shared__ float red[8];

    const int tid = threadIdx.x;
    const int a = tid >> 6, o = tid & 63;
    const int warp = tid >> 5;

    #pragma unroll
    for (int t = 0; t < 16; t++) {
        int lin = tid + t * 256;
        W2s[lin >> 6][lin & 63] = __ldg(&W2[lin]);
    }
    const float b1o = b1[o];
    const float b2o = b2[o];
    const float w3o = W3[o];
    const float b30 = b3[0];

    for (int batch = 0; batch < 4; batch++) {
        const int atom = blockIdx.x * 16 + batch * 4 + a;

        float pre = b1o;
        #pragma unroll
        for (int s = 0; s < KSPLIT; s++)
            pre += g_h1p[s * NAT * 64 + atom * 64 + o];
        h1s[a][o] = tanhf(pre);
        __syncthreads();

        float acc = b2o;
        #pragma unroll
        for (int k = 0; k < 64; k++) acc += h1s[a][k] * W2s[k][o];
        float v = tanhf(acc) * w3o;

        #pragma unroll
        for (int d = 16; d > 0; d >>= 1) v += __shfl_down_sync(0xffffffffu, v, d);
        if ((tid & 31) == 0) red[warp] = v;
        __syncthreads();
        if (o == 0) out[atom] = red[2 * a] + red[2 * a + 1] + b30;
        __syncthreads();    // h1s/red reuse safe for next batch
    }
}

// ---------------------------------------------------------------------------
extern "C" void kernel_launch(void* const* d_in, const int* in_sizes, int n_in,
                              void* d_out, int out_size)
{
    const float* pos    = (const float*)d_in[0];
    const float* spec   = (const float*)d_in[1];
    const float* kn_rad = (const float*)d_in[2];
    const float* kn_ang = (const float*)d_in[3];
    const float* rbf_w  = (const float*)d_in[4];
    const float* rbf_b  = (const float*)d_in[5];
    const float* rbf_aw = (const float*)d_in[6];
    const float* rbf_ab = (const float*)d_in[7];
    const float* W1     = (const float*)d_in[8];
    const float* b1     = (const float*)d_in[9];
    const float* W2     = (const float*)d_in[10];
    const float* b2     = (const float*)d_in[11];
    const float* W3     = (const float*)d_in[12];
    const float* b3     = (const float*)d_in[13];

    posT_kernel<<<(3 * NAT + 255) / 256, 256>>>(pos);
    feat_kernel<<<NAT, BLK_A>>>(pos, spec, kn_rad, kn_ang,
                                rbf_w, rbf_b, rbf_aw, rbf_ab);
    dim3 gb(NAT / BM, KSPLIT);
    gemm1_kernel<<<gb, 256>>>(W1);
    mlp23_kernel<<<NAT / 16, 256>>>(b1, W2, b2, W3, b3, (float*)d_out);
}